// round 7
// baseline (speedup 1.0000x reference)
#include <cuda_runtime.h>
#include <cuda_bf16.h>

#define NPTS   8192
#define KNBR   64
#define CIN    64
#define H1DIM  64
#define H2DIM  128
#define ODIM   256
#define R2     0.015625f   // 0.125^2 exactly
#define CAP    192         // candidate cap (mean ~60 in-radius)

typedef unsigned long long ull;

// Scratch (device globals; no allocation allowed)
__device__ int    g_nbr[NPTS * KNBR];
__device__ float  g_G  [NPTS * CIN];        // x @ W1[:64] + b1
__device__ float  g_AGG[NPTS * H2DIM];      // max-aggregated h2
__device__ float2 g_W2d[H1DIM * H2DIM];     // W2 duplicated (w,w)
__device__ float2 g_Wgd[H2DIM * ODIM];      // Wg duplicated (w,w)
__device__ float4 g_pos4[NPTS];             // (x, y, z, |p|^2) packed

__device__ __forceinline__ void fma2(ull& d, ull a, ull b) {
    asm("fma.rn.f32x2 %0, %1, %2, %0;" : "+l"(d) : "l"(a), "l"(b));
}

// ---------------------------------------------------------------------------
// Prep: duplicate W2 / Wg entries into (w,w) float2; pack pos -> (x,y,z,sq).
// ---------------------------------------------------------------------------
__global__ void prep_kernel(const float* __restrict__ W2, const float* __restrict__ Wg,
                            const float* __restrict__ pos, int n)
{
    int t = blockIdx.x * 256 + threadIdx.x;
    if (t < H1DIM * H2DIM) {
        float w = W2[t];
        g_W2d[t] = make_float2(w, w);
    }
    int t2 = t - H1DIM * H2DIM;
    if (t2 >= 0 && t2 < H2DIM * ODIM) {
        float w = Wg[t2];
        g_Wgd[t2] = make_float2(w, w);
    }
    if (t < n) {
        const float px = pos[3 * t + 0];
        const float py = pos[3 * t + 1];
        const float pz = pos[3 * t + 2];
        g_pos4[t] = make_float4(px, py, pz, px * px + py * py + pz * pz);
    }
}

// ---------------------------------------------------------------------------
// KNN: 4 target points per block, 256 threads share the j-sweep over packed
// pos4. Radius filter into shared candidate lists; exact (d2,idx) rank
// selection if count > K (matches jax top_k tie-breaking); pad with self.
// ---------------------------------------------------------------------------
__global__ void __launch_bounds__(256) knn_kernel(int n)
{
    __shared__ float cd2 [4][CAP];
    __shared__ int   cidx[4][CAP];
    __shared__ int   cnt[4];

    const int tid = threadIdx.x;
    const int i0  = blockIdx.x * 4;
    if (tid < 4) cnt[tid] = 0;
    __syncthreads();

    float qx[4], qy[4], qz[4], sqi[4];
    #pragma unroll
    for (int t = 0; t < 4; t++) {
        int i = i0 + t; if (i >= n) i = n - 1;
        const float4 q = g_pos4[i];
        qx[t] = q.x; qy[t] = q.y; qz[t] = q.z; sqi[t] = q.w;
    }

    for (int j = tid; j < n; j += 256) {
        const float4 p = g_pos4[j];
        #pragma unroll
        for (int t = 0; t < 4; t++) {
            const float dot = p.x * qx[t] + p.y * qy[t] + p.z * qz[t];
            const float d2  = (sqi[t] + p.w) - 2.0f * dot;   // same formula as reference
            if (d2 <= R2) {
                int pslot = atomicAdd(&cnt[t], 1);
                if (pslot < CAP) { cd2[t][pslot] = d2; cidx[t][pslot] = j; }
            }
        }
    }
    __syncthreads();

    const int t = tid >> 6;        // target within block
    const int l = tid & 63;
    const int i = i0 + t;
    if (i >= n) return;

    int M = cnt[t]; if (M > CAP) M = CAP;

    if (M <= KNBR) {
        g_nbr[i * KNBR + l] = (l < M) ? cidx[t][l] : i;   // pad with self
    } else {
        for (int m = l; m < M; m += 64) {
            const float dm = cd2[t][m];
            const int   im = cidx[t][m];
            int rank = 0;
            for (int q = 0; q < M; q++) {
                const float dq = cd2[t][q];
                rank += (dq < dm) || (dq == dm && cidx[t][q] < im);
            }
            if (rank < KNBR) g_nbr[i * KNBR + rank] = cidx[t][m];
        }
    }
}

// ---------------------------------------------------------------------------
// G precompute: G = x @ W1[0:64,:] + b1   (per-source-point layer-1 part)
// ---------------------------------------------------------------------------
__global__ void __launch_bounds__(128) g_kernel(
    const float* __restrict__ x, const float* __restrict__ W1,
    const float* __restrict__ b1, int n)
{
    __shared__ __align__(16) float xs[8 * 64];
    const int tid = threadIdx.x;
    const int i0  = blockIdx.x * 8;

    for (int idx = tid; idx < 512; idx += 128) {
        int p = idx >> 6, d = idx & 63;
        xs[idx] = (i0 + p < n) ? x[(size_t)(i0 + p) * 64 + d] : 0.0f;
    }
    __syncthreads();

    const int p  = tid >> 4;
    const int c4 = (tid & 15) * 4;
    if (i0 + p >= n) return;

    float4 acc = *(const float4*)&b1[c4];
    const float* xr = &xs[p * 64];
    #pragma unroll 8
    for (int d = 0; d < 64; d++) {
        const float xv = xr[d];
        float4 w = *(const float4*)&W1[d * 64 + c4];
        acc.x = fmaf(xv, w.x, acc.x);
        acc.y = fmaf(xv, w.y, acc.y);
        acc.z = fmaf(xv, w.z, acc.z);
        acc.w = fmaf(xv, w.w, acc.w);
    }
    *(float4*)&g_G[(size_t)(i0 + p) * 64 + c4] = acc;
}

// ---------------------------------------------------------------------------
// Main edge kernel: one block per point, 128 threads.
// Phase A: batch-load all 8 g_G float4 (MLP=8, one latency exposure) then
//          h1[c][nk] = relu(G[j] + rel @ W1[64:67]) into shared [c][nk].
// Phase B: register tile 4 channels x 16 neighbors per thread; per d-step
//          4 broadcast LDS.128 + 4 coalesced LDG.64 feed 32 packed f32x2 FMA.
// ---------------------------------------------------------------------------
__global__ void __launch_bounds__(128, 4) compute_kernel(
    const float* __restrict__ pos, const float* __restrict__ W1,
    const float* __restrict__ b2, int n)
{
    __shared__ __align__(16) float H1s[H1DIM * 68];   // [c][nk], stride 68
    __shared__ int   nbr_s[KNBR];
    __shared__ float relx[KNBR], rely[KNBR], relz[KNBR];
    __shared__ float red[4][H2DIM];                   // per-ngroup channel maxes

    const int i   = blockIdx.x;
    const int tid = threadIdx.x;
    if (i >= n) return;

    if (tid < KNBR) {
        const int j = g_nbr[i * KNBR + tid];
        nbr_s[tid] = j;
        relx[tid] = pos[3 * j + 0] - pos[3 * i + 0];
        rely[tid] = pos[3 * j + 1] - pos[3 * i + 1];
        relz[tid] = pos[3 * j + 2] - pos[3 * i + 2];
    }
    __syncthreads();

    // ---- Phase A ----
    {
        const int nk0 = tid & 7;
        const int c4  = (tid >> 3) * 4;

        // batch all scattered g_G loads first (MLP=8 -> one L2 latency)
        float4 g4[8];
        #pragma unroll
        for (int it = 0; it < 8; it++)
            g4[it] = *(const float4*)&g_G[(size_t)nbr_s[nk0 + it * 8] * 64 + c4];

        const float4 wx = *(const float4*)&W1[64 * 64 + c4];
        const float4 wy = *(const float4*)&W1[65 * 64 + c4];
        const float4 wz = *(const float4*)&W1[66 * 64 + c4];

        #pragma unroll
        for (int it = 0; it < 8; it++) {
            const int nk = nk0 + it * 8;
            const float rx = relx[nk], ry = rely[nk], rz = relz[nk];
            float4 a;
            a.x = fmaf(rx, wx.x, fmaf(ry, wy.x, fmaf(rz, wz.x, g4[it].x)));
            a.y = fmaf(rx, wx.y, fmaf(ry, wy.y, fmaf(rz, wz.y, g4[it].y)));
            a.z = fmaf(rx, wx.z, fmaf(ry, wy.z, fmaf(rz, wz.z, g4[it].z)));
            a.w = fmaf(rx, wx.w, fmaf(ry, wy.w, fmaf(rz, wz.w, g4[it].w)));
            H1s[(c4 + 0) * 68 + nk] = fmaxf(a.x, 0.0f);
            H1s[(c4 + 1) * 68 + nk] = fmaxf(a.y, 0.0f);
            H1s[(c4 + 2) * 68 + nk] = fmaxf(a.z, 0.0f);
            H1s[(c4 + 3) * 68 + nk] = fmaxf(a.w, 0.0f);
        }
    }
    __syncthreads();

    // ---- Phase B: layer 2 + max-agg, 4ch x 16nbr register tile ----
    {
        const int cg = tid & 31;        // channel group lane (0..31)
        const int ng = tid >> 5;        // neighbor group (0..3) -> nbrs [16ng,16ng+16)
        const int nb = ng * 16;

        ull acc[4][8];
        #pragma unroll
        for (int k = 0; k < 4; k++)
            #pragma unroll
            for (int p = 0; p < 8; p++) acc[k][p] = 0ull;

        const ull*   wp = reinterpret_cast<const ull*>(g_W2d) + cg;  // + d*128
        const float* hr = &H1s[nb];

        #pragma unroll 4
        for (int d = 0; d < H1DIM; d++) {
            const ull w0 = wp[0];
            const ull w1 = wp[32];
            const ull w2 = wp[64];
            const ull w3 = wp[96];
            wp += H2DIM;
            #pragma unroll
            for (int p = 0; p < 4; p++) {
                const ulonglong2 hv = *reinterpret_cast<const ulonglong2*>(hr + 4 * p);
                fma2(acc[0][2 * p + 0], hv.x, w0);
                fma2(acc[0][2 * p + 1], hv.y, w0);
                fma2(acc[1][2 * p + 0], hv.x, w1);
                fma2(acc[1][2 * p + 1], hv.y, w1);
                fma2(acc[2][2 * p + 0], hv.x, w2);
                fma2(acc[2][2 * p + 1], hv.y, w2);
                fma2(acc[3][2 * p + 0], hv.x, w3);
                fma2(acc[3][2 * p + 1], hv.y, w3);
            }
            hr += 68;
        }

        // local max over this thread's 16 neighbors, per channel
        #pragma unroll
        for (int k = 0; k < 4; k++) {
            float m = -1e30f;
            #pragma unroll
            for (int p = 0; p < 8; p++) {
                const float lo = __uint_as_float((unsigned)(acc[k][p] & 0xffffffffu));
                const float hi = __uint_as_float((unsigned)(acc[k][p] >> 32));
                m = fmaxf(m, fmaxf(lo, hi));
            }
            red[ng][32 * k + cg] = m;
        }
    }
    __syncthreads();

    // cross-ngroup reduction; relu(max+b2) == max relu(z+b2) (max monotone)
    {
        const int c = tid;
        const float v = fmaxf(fmaxf(red[0][c], red[1][c]),
                              fmaxf(red[2][c], red[3][c]));
        g_AGG[(size_t)i * H2DIM + c] = fmaxf(v + b2[c], 0.0f);
    }
}

// ---------------------------------------------------------------------------
// Global layer GEMM: out = relu(AGG @ Wg + bg). 32-point tiles, 256 threads,
// packed f32x2 accumulation over rows, Wg duplicated pairs from g_Wgd.
// ---------------------------------------------------------------------------
__global__ void __launch_bounds__(256) gemm_kernel(
    const float* __restrict__ bg, float* __restrict__ out, int n)
{
    __shared__ __align__(16) float As[H2DIM * 36];   // [d][r], stride 36
    const int tid = threadIdx.x;
    const int i0  = blockIdx.x * 32;

    for (int idx = tid; idx < 32 * H2DIM; idx += 256) {
        const int r = idx >> 7, d = idx & 127;
        const int row = (i0 + r < n) ? (i0 + r) : (n - 1);
        As[d * 36 + r] = g_AGG[(size_t)row * H2DIM + d];
    }
    __syncthreads();

    const int c = tid;   // output channel 0..255
    ull acc[16];
    #pragma unroll
    for (int p = 0; p < 16; p++) acc[p] = 0ull;

    const ull* wp = reinterpret_cast<const ull*>(g_Wgd) + c;
    #pragma unroll 2
    for (int d = 0; d < H2DIM; d++) {
        const ull wd = *wp; wp += ODIM;
        const float* ar = &As[d * 36];
        #pragma unroll
        for (int p = 0; p < 8; p++) {
            const ulonglong2 av = *reinterpret_cast<const ulonglong2*>(ar + 4 * p);
            fma2(acc[2 * p + 0], av.x, wd);
            fma2(acc[2 * p + 1], av.y, wd);
        }
    }

    const float bc = bg[c];
    #pragma unroll
    for (int k = 0; k < 16; k++) {          // acc[k] -> rows (2k, 2k+1)
        const float lo = __uint_as_float((unsigned)(acc[k] & 0xffffffffu));
        const float hi = __uint_as_float((unsigned)(acc[k] >> 32));
        const int r0 = i0 + 2 * k, r1 = r0 + 1;
        if (r0 < n) out[(size_t)r0 * ODIM + c] = fmaxf(lo + bc, 0.0f);
        if (r1 < n) out[(size_t)r1 * ODIM + c] = fmaxf(hi + bc, 0.0f);
    }
}

// ---------------------------------------------------------------------------
extern "C" void kernel_launch(void* const* d_in, const int* in_sizes, int n_in,
                              void* d_out, int out_size)
{
    const float* x   = (const float*)d_in[0];
    const float* pos = (const float*)d_in[1];
    // d_in[2] = batch (all zeros, unused)
    const float* W1  = (const float*)d_in[3];
    const float* b1  = (const float*)d_in[4];
    const float* W2  = (const float*)d_in[5];
    const float* b2  = (const float*)d_in[6];
    const float* Wg  = (const float*)d_in[7];
    const float* bg  = (const float*)d_in[8];
    float* out = (float*)d_out;

    const int n = in_sizes[2];   // batch vector length == N

    int prep_work = H1DIM * H2DIM + H2DIM * ODIM;
    if (n > prep_work) prep_work = n;
    prep_kernel<<<(prep_work + 255) / 256, 256>>>(W2, Wg, pos, n);
    knn_kernel<<<(n + 3) / 4, 256>>>(n);
    g_kernel<<<(n + 7) / 8, 128>>>(x, W1, b1, n);
    compute_kernel<<<n, 128>>>(pos, W1, b2, n);
    gemm_kernel<<<(n + 31) / 32, 256>>>(bg, out, n);
}

// round 8
// speedup vs baseline: 1.7444x; 1.7444x over previous
#include <cuda_runtime.h>
#include <cuda_bf16.h>

#define NPTS   8192
#define KNBR   64
#define CIN    64
#define H1DIM  64
#define H2DIM  128
#define ODIM   256
#define R2     0.015625f   // 0.125^2 exactly
#define CAP    192         // candidate cap (mean ~60 in-radius)
#define GRID   8           // 8x8x8 cells, width 0.125 == R
#define NCELLS (GRID * GRID * GRID)

typedef unsigned long long ull;

// Scratch (device globals; no allocation allowed)
__device__ int    g_nbr[NPTS * KNBR];
__device__ float  g_G  [NPTS * CIN];        // x @ W1[:64] + b1
__device__ float  g_AGG[NPTS * H2DIM];      // max-aggregated h2
__device__ float2 g_W2d[H1DIM * H2DIM];     // W2 duplicated (w,w)
__device__ float2 g_Wgd[H2DIM * ODIM];      // Wg duplicated (w,w)
__device__ float4 g_pos4[NPTS];             // (x, y, z, |p|^2) packed
// spatial grid
__device__ int    g_cell_cnt[NCELLS];
__device__ int    g_cell_start[NCELLS];
__device__ int    g_cell_fill[NCELLS];
__device__ float4 g_pos4s[NPTS];            // pos4 sorted by cell
__device__ int    g_ptid[NPTS];             // original index, sorted by cell

__device__ __forceinline__ void fma2(ull& d, ull a, ull b) {
    asm("fma.rn.f32x2 %0, %1, %2, %0;" : "+l"(d) : "l"(a), "l"(b));
}

__device__ __forceinline__ int cell_of(float v) {
    int c = (int)(v * (float)GRID);
    return min(max(c, 0), GRID - 1);
}

// ---------------------------------------------------------------------------
// Prep: duplicate W2 / Wg into (w,w) float2; pack pos -> (x,y,z,sq); zero grid.
// ---------------------------------------------------------------------------
__global__ void prep_kernel(const float* __restrict__ W2, const float* __restrict__ Wg,
                            const float* __restrict__ pos, int n)
{
    int t = blockIdx.x * 256 + threadIdx.x;
    if (t < H1DIM * H2DIM) {
        float w = W2[t];
        g_W2d[t] = make_float2(w, w);
    }
    int t2 = t - H1DIM * H2DIM;
    if (t2 >= 0 && t2 < H2DIM * ODIM) {
        float w = Wg[t2];
        g_Wgd[t2] = make_float2(w, w);
    }
    if (t < n) {
        const float px = pos[3 * t + 0];
        const float py = pos[3 * t + 1];
        const float pz = pos[3 * t + 2];
        g_pos4[t] = make_float4(px, py, pz, px * px + py * py + pz * pz);
    }
    if (t < NCELLS) {
        g_cell_cnt[t]  = 0;
        g_cell_fill[t] = 0;
    }
}

// ---------------------------------------------------------------------------
// Counting sort: histogram -> exclusive scan -> scatter (pos4 + ids by cell)
// ---------------------------------------------------------------------------
__global__ void hist_kernel(int n)
{
    int t = blockIdx.x * 256 + threadIdx.x;
    if (t >= n) return;
    const float4 p = g_pos4[t];
    const int c = (cell_of(p.z) * GRID + cell_of(p.y)) * GRID + cell_of(p.x);
    atomicAdd(&g_cell_cnt[c], 1);
}

__global__ void scan_kernel()
{
    __shared__ int buf[NCELLS];
    const int t = threadIdx.x;
    const int v = g_cell_cnt[t];
    buf[t] = v;
    __syncthreads();
    for (int o = 1; o < NCELLS; o <<= 1) {
        int u = (t >= o) ? buf[t - o] : 0;
        __syncthreads();
        buf[t] += u;
        __syncthreads();
    }
    g_cell_start[t] = buf[t] - v;   // exclusive prefix
}

__global__ void scatter_kernel(int n)
{
    int t = blockIdx.x * 256 + threadIdx.x;
    if (t >= n) return;
    const float4 p = g_pos4[t];
    const int c = (cell_of(p.z) * GRID + cell_of(p.y)) * GRID + cell_of(p.x);
    const int slot = g_cell_start[c] + atomicAdd(&g_cell_fill[c], 1);
    g_pos4s[slot] = p;
    g_ptid[slot]  = t;
}

// ---------------------------------------------------------------------------
// Grid KNN: one warp per target point. Sweep the 27 neighboring cells
// (cell width == R, so this covers every within-radius candidate exactly).
// Radius filter into shared candidate list; exact (d2,idx) rank selection if
// count > K (matches jax top_k tie-breaking); pad with self.
// ---------------------------------------------------------------------------
__global__ void __launch_bounds__(128) knn_kernel(int n)
{
    __shared__ float cd2 [4][CAP];
    __shared__ int   cidx[4][CAP];
    __shared__ int   cnt[4];

    const int w    = threadIdx.x >> 5;     // warp = target slot
    const int lane = threadIdx.x & 31;
    const int i    = blockIdx.x * 4 + w;
    if (i >= n) return;
    if (lane == 0) cnt[w] = 0;
    __syncwarp();

    const float4 q = g_pos4[i];
    const int cx = cell_of(q.x), cy = cell_of(q.y), cz = cell_of(q.z);

    const int zlo = max(cz - 1, 0), zhi = min(cz + 1, GRID - 1);
    const int ylo = max(cy - 1, 0), yhi = min(cy + 1, GRID - 1);
    const int xlo = max(cx - 1, 0), xhi = min(cx + 1, GRID - 1);

    for (int z = zlo; z <= zhi; z++)
        for (int y = ylo; y <= yhi; y++) {
            // x-range of cells is contiguous in the sorted array
            const int c0 = (z * GRID + y) * GRID + xlo;
            const int c1 = (z * GRID + y) * GRID + xhi;
            const int s0 = g_cell_start[c0];
            const int s1 = g_cell_start[c1] + g_cell_cnt[c1];
            for (int s = s0 + lane; s < s1; s += 32) {
                const float4 p = g_pos4s[s];
                const float dot = p.x * q.x + p.y * q.y + p.z * q.z;
                const float d2  = (q.w + p.w) - 2.0f * dot;   // same formula as reference
                if (d2 <= R2) {
                    int slot = atomicAdd(&cnt[w], 1);
                    if (slot < CAP) { cd2[w][slot] = d2; cidx[w][slot] = g_ptid[s]; }
                }
            }
        }
    __syncwarp();

    int M = cnt[w]; if (M > CAP) M = CAP;

    if (M <= KNBR) {
        for (int l = lane; l < KNBR; l += 32)
            g_nbr[i * KNBR + l] = (l < M) ? cidx[w][l] : i;   // pad with self
    } else {
        for (int m = lane; m < M; m += 32) {
            const float dm = cd2[w][m];
            const int   im = cidx[w][m];
            int rank = 0;
            for (int qq = 0; qq < M; qq++) {
                const float dq = cd2[w][qq];
                rank += (dq < dm) || (dq == dm && cidx[w][qq] < im);
            }
            if (rank < KNBR) g_nbr[i * KNBR + rank] = cidx[w][m];
        }
    }
}

// ---------------------------------------------------------------------------
// G precompute: G = x @ W1[0:64,:] + b1   (per-source-point layer-1 part)
// ---------------------------------------------------------------------------
__global__ void __launch_bounds__(128) g_kernel(
    const float* __restrict__ x, const float* __restrict__ W1,
    const float* __restrict__ b1, int n)
{
    __shared__ __align__(16) float xs[8 * 64];
    const int tid = threadIdx.x;
    const int i0  = blockIdx.x * 8;

    for (int idx = tid; idx < 512; idx += 128) {
        int p = idx >> 6, d = idx & 63;
        xs[idx] = (i0 + p < n) ? x[(size_t)(i0 + p) * 64 + d] : 0.0f;
    }
    __syncthreads();

    const int p  = tid >> 4;
    const int c4 = (tid & 15) * 4;
    if (i0 + p >= n) return;

    float4 acc = *(const float4*)&b1[c4];
    const float* xr = &xs[p * 64];
    #pragma unroll 8
    for (int d = 0; d < 64; d++) {
        const float xv = xr[d];
        float4 w = *(const float4*)&W1[d * 64 + c4];
        acc.x = fmaf(xv, w.x, acc.x);
        acc.y = fmaf(xv, w.y, acc.y);
        acc.z = fmaf(xv, w.z, acc.z);
        acc.w = fmaf(xv, w.w, acc.w);
    }
    *(float4*)&g_G[(size_t)(i0 + p) * 64 + c4] = acc;
}

// ---------------------------------------------------------------------------
// Main edge kernel: one block per point, 128 threads.  (UNCHANGED from the
// proven 197us version — protect the win.)
// ---------------------------------------------------------------------------
__global__ void __launch_bounds__(128, 4) compute_kernel(
    const float* __restrict__ pos, const float* __restrict__ W1,
    const float* __restrict__ b2, int n)
{
    __shared__ __align__(16) float H1s[H1DIM * 68];   // [c][nk], stride 68
    __shared__ int   nbr_s[KNBR];
    __shared__ float relx[KNBR], rely[KNBR], relz[KNBR];
    __shared__ float red[4][H2DIM];                   // per-ngroup channel maxes

    const int i   = blockIdx.x;
    const int tid = threadIdx.x;
    if (i >= n) return;

    if (tid < KNBR) {
        const int j = g_nbr[i * KNBR + tid];
        nbr_s[tid] = j;
        relx[tid] = pos[3 * j + 0] - pos[3 * i + 0];
        rely[tid] = pos[3 * j + 1] - pos[3 * i + 1];
        relz[tid] = pos[3 * j + 2] - pos[3 * i + 2];
    }
    __syncthreads();

    // ---- Phase A ----
    {
        const int nk0 = tid & 7;
        const int c4  = (tid >> 3) * 4;

        // batch all scattered g_G loads first (MLP=8 -> one L2 latency)
        float4 g4[8];
        #pragma unroll
        for (int it = 0; it < 8; it++)
            g4[it] = *(const float4*)&g_G[(size_t)nbr_s[nk0 + it * 8] * 64 + c4];

        const float4 wx = *(const float4*)&W1[64 * 64 + c4];
        const float4 wy = *(const float4*)&W1[65 * 64 + c4];
        const float4 wz = *(const float4*)&W1[66 * 64 + c4];

        #pragma unroll
        for (int it = 0; it < 8; it++) {
            const int nk = nk0 + it * 8;
            const float rx = relx[nk], ry = rely[nk], rz = relz[nk];
            float4 a;
            a.x = fmaf(rx, wx.x, fmaf(ry, wy.x, fmaf(rz, wz.x, g4[it].x)));
            a.y = fmaf(rx, wx.y, fmaf(ry, wy.y, fmaf(rz, wz.y, g4[it].y)));
            a.z = fmaf(rx, wx.z, fmaf(ry, wy.z, fmaf(rz, wz.z, g4[it].z)));
            a.w = fmaf(rx, wx.w, fmaf(ry, wy.w, fmaf(rz, wz.w, g4[it].w)));
            H1s[(c4 + 0) * 68 + nk] = fmaxf(a.x, 0.0f);
            H1s[(c4 + 1) * 68 + nk] = fmaxf(a.y, 0.0f);
            H1s[(c4 + 2) * 68 + nk] = fmaxf(a.z, 0.0f);
            H1s[(c4 + 3) * 68 + nk] = fmaxf(a.w, 0.0f);
        }
    }
    __syncthreads();

    // ---- Phase B: layer 2 + max-agg, 4ch x 16nbr register tile ----
    {
        const int cg = tid & 31;        // channel group lane (0..31)
        const int ng = tid >> 5;        // neighbor group (0..3) -> nbrs [16ng,16ng+16)
        const int nb = ng * 16;

        ull acc[4][8];
        #pragma unroll
        for (int k = 0; k < 4; k++)
            #pragma unroll
            for (int p = 0; p < 8; p++) acc[k][p] = 0ull;

        const ull*   wp = reinterpret_cast<const ull*>(g_W2d) + cg;  // + d*128
        const float* hr = &H1s[nb];

        #pragma unroll 4
        for (int d = 0; d < H1DIM; d++) {
            const ull w0 = wp[0];
            const ull w1 = wp[32];
            const ull w2 = wp[64];
            const ull w3 = wp[96];
            wp += H2DIM;
            #pragma unroll
            for (int p = 0; p < 4; p++) {
                const ulonglong2 hv = *reinterpret_cast<const ulonglong2*>(hr + 4 * p);
                fma2(acc[0][2 * p + 0], hv.x, w0);
                fma2(acc[0][2 * p + 1], hv.y, w0);
                fma2(acc[1][2 * p + 0], hv.x, w1);
                fma2(acc[1][2 * p + 1], hv.y, w1);
                fma2(acc[2][2 * p + 0], hv.x, w2);
                fma2(acc[2][2 * p + 1], hv.y, w2);
                fma2(acc[3][2 * p + 0], hv.x, w3);
                fma2(acc[3][2 * p + 1], hv.y, w3);
            }
            hr += 68;
        }

        // local max over this thread's 16 neighbors, per channel
        #pragma unroll
        for (int k = 0; k < 4; k++) {
            float m = -1e30f;
            #pragma unroll
            for (int p = 0; p < 8; p++) {
                const float lo = __uint_as_float((unsigned)(acc[k][p] & 0xffffffffu));
                const float hi = __uint_as_float((unsigned)(acc[k][p] >> 32));
                m = fmaxf(m, fmaxf(lo, hi));
            }
            red[ng][32 * k + cg] = m;
        }
    }
    __syncthreads();

    // cross-ngroup reduction; relu(max+b2) == max relu(z+b2) (max monotone)
    {
        const int c = tid;
        const float v = fmaxf(fmaxf(red[0][c], red[1][c]),
                              fmaxf(red[2][c], red[3][c]));
        g_AGG[(size_t)i * H2DIM + c] = fmaxf(v + b2[c], 0.0f);
    }
}

// ---------------------------------------------------------------------------
// Global layer GEMM: out = relu(AGG @ Wg + bg). 32-point tiles, 256 threads,
// packed f32x2 accumulation over rows, Wg duplicated pairs from g_Wgd.
// ---------------------------------------------------------------------------
__global__ void __launch_bounds__(256) gemm_kernel(
    const float* __restrict__ bg, float* __restrict__ out, int n)
{
    __shared__ __align__(16) float As[H2DIM * 36];   // [d][r], stride 36
    const int tid = threadIdx.x;
    const int i0  = blockIdx.x * 32;

    for (int idx = tid; idx < 32 * H2DIM; idx += 256) {
        const int r = idx >> 7, d = idx & 127;
        const int row = (i0 + r < n) ? (i0 + r) : (n - 1);
        As[d * 36 + r] = g_AGG[(size_t)row * H2DIM + d];
    }
    __syncthreads();

    const int c = tid;   // output channel 0..255
    ull acc[16];
    #pragma unroll
    for (int p = 0; p < 16; p++) acc[p] = 0ull;

    const ull* wp = reinterpret_cast<const ull*>(g_Wgd) + c;
    #pragma unroll 2
    for (int d = 0; d < H2DIM; d++) {
        const ull wd = *wp; wp += ODIM;
        const float* ar = &As[d * 36];
        #pragma unroll
        for (int p = 0; p < 8; p++) {
            const ulonglong2 av = *reinterpret_cast<const ulonglong2*>(ar + 4 * p);
            fma2(acc[2 * p + 0], av.x, wd);
            fma2(acc[2 * p + 1], av.y, wd);
        }
    }

    const float bc = bg[c];
    #pragma unroll
    for (int k = 0; k < 16; k++) {          // acc[k] -> rows (2k, 2k+1)
        const float lo = __uint_as_float((unsigned)(acc[k] & 0xffffffffu));
        const float hi = __uint_as_float((unsigned)(acc[k] >> 32));
        const int r0 = i0 + 2 * k, r1 = r0 + 1;
        if (r0 < n) out[(size_t)r0 * ODIM + c] = fmaxf(lo + bc, 0.0f);
        if (r1 < n) out[(size_t)r1 * ODIM + c] = fmaxf(hi + bc, 0.0f);
    }
}

// ---------------------------------------------------------------------------
extern "C" void kernel_launch(void* const* d_in, const int* in_sizes, int n_in,
                              void* d_out, int out_size)
{
    const float* x   = (const float*)d_in[0];
    const float* pos = (const float*)d_in[1];
    // d_in[2] = batch (all zeros, unused)
    const float* W1  = (const float*)d_in[3];
    const float* b1  = (const float*)d_in[4];
    const float* W2  = (const float*)d_in[5];
    const float* b2  = (const float*)d_in[6];
    const float* Wg  = (const float*)d_in[7];
    const float* bg  = (const float*)d_in[8];
    float* out = (float*)d_out;

    const int n = in_sizes[2];   // batch vector length == N

    int prep_work = H1DIM * H2DIM + H2DIM * ODIM;
    if (n > prep_work) prep_work = n;
    prep_kernel<<<(prep_work + 255) / 256, 256>>>(W2, Wg, pos, n);
    hist_kernel<<<(n + 255) / 256, 256>>>(n);
    scan_kernel<<<1, NCELLS>>>();
    scatter_kernel<<<(n + 255) / 256, 256>>>(n);
    knn_kernel<<<(n + 3) / 4, 128>>>(n);
    g_kernel<<<(n + 7) / 8, 128>>>(x, W1, b1, n);
    compute_kernel<<<n, 128>>>(pos, W1, b2, n);
    gemm_kernel<<<(n + 31) / 32, 256>>>(bg, out, n);
}

// round 12
// speedup vs baseline: 3.1264x; 1.7923x over previous
#include <cuda_runtime.h>
#include <cuda_bf16.h>
#include <cstdint>

#define NPTS   8192
#define KNBR   64
#define CIN    64
#define H1DIM  64
#define H2DIM  128
#define ODIM   256
#define R2     0.015625f   // 0.125^2 exactly
#define CAP    192         // candidate cap (mean ~60 in-radius)
#define GRID   8           // 8x8x8 cells, width 0.125 == R
#define NCELLS (GRID * GRID * GRID)

#define BSTRIDE 72         // halves per row of B planes (144B, 16B-aligned, conflict-free)

typedef unsigned long long ull;

// ---- scratch (device globals; no allocation allowed) ----------------------
__device__ int    g_nbr[NPTS * KNBR];
__device__ float  g_G  [NPTS * CIN];        // x @ W1[:64] + b1
__device__ float  g_AGG[NPTS * H2DIM];      // max-aggregated h2
__device__ float2 g_Wgd[H2DIM * ODIM];      // Wg duplicated (w,w)
__device__ float4 g_pos4[NPTS];             // (x, y, z, |p|^2)
__device__ uint4  g_AF4[64 * 32];           // pre-baked W2^T mma A-fragments
                                            // frag = ((w*2+mt)*4+kt)*2+plane, [frag][lane]
// spatial grid
__device__ int    g_cell_cnt[NCELLS];
__device__ int    g_cell_start[NCELLS];
__device__ int    g_cell_fill[NCELLS];
__device__ float4 g_pos4s[NPTS];
__device__ int    g_ptid[NPTS];

__device__ __forceinline__ void fma2(ull& d, ull a, ull b) {
    asm("fma.rn.f32x2 %0, %1, %2, %0;" : "+l"(d) : "l"(a), "l"(b));
}
__device__ __forceinline__ int cell_of(float v) {
    int c = (int)(v * (float)GRID);
    return min(max(c, 0), GRID - 1);
}
// round-to-nearest-even fp32 -> bf16 (bits)
__device__ __forceinline__ unsigned bf16rn(float f) {
    unsigned u = __float_as_uint(f);
    return (u + 0x7FFFu + ((u >> 16) & 1u)) >> 16;
}
__device__ __forceinline__ uint32_t smem_to_u32(const void* p) {
    uint32_t a;
    asm("{ .reg .u64 t; cvta.to.shared.u64 t, %1; cvt.u32.u64 %0, t; }" : "=r"(a) : "l"(p));
    return a;
}

// mma.sync m16n8k16 bf16, fp32 accum (baseline PTX; valid on compute_103)
#define MMA_BF16(acc, a, b0v, b1v) \
    asm volatile("mma.sync.aligned.m16n8k16.row.col.f32.bf16.bf16.f32 " \
        "{%0,%1,%2,%3}, {%4,%5,%6,%7}, {%8,%9}, {%0,%1,%2,%3};" \
        : "+f"((acc)[0]), "+f"((acc)[1]), "+f"((acc)[2]), "+f"((acc)[3]) \
        : "r"((a).x), "r"((a).y), "r"((a).z), "r"((a).w), "r"(b0v), "r"(b1v))

#define LDSM_X4(r0, r1, r2, r3, addr) \
    asm volatile("ldmatrix.sync.aligned.m8n8.x4.shared.b16 {%0,%1,%2,%3}, [%4];" \
        : "=r"(r0), "=r"(r1), "=r"(r2), "=r"(r3) : "r"(addr))

// ---------------------------------------------------------------------------
// Prep: Wg dup pairs; pos4 pack; zero grid counters; bake W2^T A-fragments.
// ---------------------------------------------------------------------------
__global__ void prep_kernel(const float* __restrict__ W2, const float* __restrict__ Wg,
                            const float* __restrict__ pos, int n)
{
    int t = blockIdx.x * 256 + threadIdx.x;
    if (t < H2DIM * ODIM) {
        float w = Wg[t];
        g_Wgd[t] = make_float2(w, w);
    }
    if (t < n) {
        const float px = pos[3 * t + 0];
        const float py = pos[3 * t + 1];
        const float pz = pos[3 * t + 2];
        g_pos4[t] = make_float4(px, py, pz, px * px + py * py + pz * pz);
    }
    if (t < NCELLS) {
        g_cell_cnt[t]  = 0;
        g_cell_fill[t] = 0;
    }
    // A-fragment baking: a0=(r,k), a1=(r+8,k), a2=(r,k+8), a3=(r+8,k+8);
    // per-lane: row = base_m + lane/4, k = base_k + 2*(lane%4)+{0,1} (low half = even k)
    int t4 = t - H2DIM * ODIM;
    if (t4 >= 0 && t4 < 64 * 32) {
        const int frag = t4 >> 5, lane = t4 & 31;
        const int plane = frag & 1;
        const int kt    = (frag >> 1) & 3;
        const int mt    = (frag >> 3) & 1;
        const int ww    = frag >> 4;
        const int r = 32 * ww + 16 * mt + (lane >> 2);
        const int k = 16 * kt + 2 * (lane & 3);
        uint32_t regs[4];
        #pragma unroll
        for (int j = 0; j < 4; j++) {
            const int rr = r + (j & 1) * 8;
            const int kk = k + (j >> 1) * 8;
            const float v0 = W2[(size_t)kk * H2DIM + rr];       // W2^T[rr][kk]
            const float v1 = W2[(size_t)(kk + 1) * H2DIM + rr];
            unsigned h0 = bf16rn(v0), h1 = bf16rn(v1);
            if (plane) {
                h0 = bf16rn(v0 - __uint_as_float(h0 << 16));
                h1 = bf16rn(v1 - __uint_as_float(h1 << 16));
            }
            regs[j] = h0 | (h1 << 16);
        }
        g_AF4[frag * 32 + lane] = make_uint4(regs[0], regs[1], regs[2], regs[3]);
    }
}

// ---------------------------------------------------------------------------
// Counting sort: histogram -> exclusive scan -> scatter
// ---------------------------------------------------------------------------
__global__ void hist_kernel(int n)
{
    int t = blockIdx.x * 256 + threadIdx.x;
    if (t >= n) return;
    const float4 p = g_pos4[t];
    const int c = (cell_of(p.z) * GRID + cell_of(p.y)) * GRID + cell_of(p.x);
    atomicAdd(&g_cell_cnt[c], 1);
}

__global__ void scan_kernel()
{
    __shared__ int buf[NCELLS];
    const int t = threadIdx.x;
    const int v = g_cell_cnt[t];
    buf[t] = v;
    __syncthreads();
    for (int o = 1; o < NCELLS; o <<= 1) {
        int u = (t >= o) ? buf[t - o] : 0;
        __syncthreads();
        buf[t] += u;
        __syncthreads();
    }
    g_cell_start[t] = buf[t] - v;
}

__global__ void scatter_kernel(int n)
{
    int t = blockIdx.x * 256 + threadIdx.x;
    if (t >= n) return;
    const float4 p = g_pos4[t];
    const int c = (cell_of(p.z) * GRID + cell_of(p.y)) * GRID + cell_of(p.x);
    const int slot = g_cell_start[c] + atomicAdd(&g_cell_fill[c], 1);
    g_pos4s[slot] = p;
    g_ptid[slot]  = t;
}

// ---------------------------------------------------------------------------
// Grid KNN: one warp per target; 27-cell sweep (cell width == R covers all).
// ---------------------------------------------------------------------------
__global__ void __launch_bounds__(128) knn_kernel(int n)
{
    __shared__ float cd2 [4][CAP];
    __shared__ int   cidx[4][CAP];
    __shared__ int   cnt[4];

    const int w    = threadIdx.x >> 5;
    const int lane = threadIdx.x & 31;
    const int i    = blockIdx.x * 4 + w;
    if (i >= n) return;
    if (lane == 0) cnt[w] = 0;
    __syncwarp();

    const float4 q = g_pos4[i];
    const int cx = cell_of(q.x), cy = cell_of(q.y), cz = cell_of(q.z);

    const int zlo = max(cz - 1, 0), zhi = min(cz + 1, GRID - 1);
    const int ylo = max(cy - 1, 0), yhi = min(cy + 1, GRID - 1);
    const int xlo = max(cx - 1, 0), xhi = min(cx + 1, GRID - 1);

    for (int z = zlo; z <= zhi; z++)
        for (int y = ylo; y <= yhi; y++) {
            const int c0 = (z * GRID + y) * GRID + xlo;
            const int c1 = (z * GRID + y) * GRID + xhi;
            const int s0 = g_cell_start[c0];
            const int s1 = g_cell_start[c1] + g_cell_cnt[c1];
            for (int s = s0 + lane; s < s1; s += 32) {
                const float4 p = g_pos4s[s];
                const float dot = p.x * q.x + p.y * q.y + p.z * q.z;
                const float d2  = (q.w + p.w) - 2.0f * dot;
                if (d2 <= R2) {
                    int slot = atomicAdd(&cnt[w], 1);
                    if (slot < CAP) { cd2[w][slot] = d2; cidx[w][slot] = g_ptid[s]; }
                }
            }
        }
    __syncwarp();

    int M = cnt[w]; if (M > CAP) M = CAP;

    if (M <= KNBR) {
        for (int l = lane; l < KNBR; l += 32)
            g_nbr[i * KNBR + l] = (l < M) ? cidx[w][l] : i;
    } else {
        for (int m = lane; m < M; m += 32) {
            const float dm = cd2[w][m];
            const int   im = cidx[w][m];
            int rank = 0;
            for (int qq = 0; qq < M; qq++) {
                const float dq = cd2[w][qq];
                rank += (dq < dm) || (dq == dm && cidx[w][qq] < im);
            }
            if (rank < KNBR) g_nbr[i * KNBR + rank] = cidx[w][m];
        }
    }
}

// ---------------------------------------------------------------------------
// G precompute: G = x @ W1[0:64,:] + b1
// ---------------------------------------------------------------------------
__global__ void __launch_bounds__(128) g_kernel(
    const float* __restrict__ x, const float* __restrict__ W1,
    const float* __restrict__ b1, int n)
{
    __shared__ __align__(16) float xs[8 * 64];
    const int tid = threadIdx.x;
    const int i0  = blockIdx.x * 8;

    for (int idx = tid; idx < 512; idx += 128) {
        int p = idx >> 6, d = idx & 63;
        xs[idx] = (i0 + p < n) ? x[(size_t)(i0 + p) * 64 + d] : 0.0f;
    }
    __syncthreads();

    const int p  = tid >> 4;
    const int c4 = (tid & 15) * 4;
    if (i0 + p >= n) return;

    float4 acc = *(const float4*)&b1[c4];
    const float* xr = &xs[p * 64];
    #pragma unroll 8
    for (int d = 0; d < 64; d++) {
        const float xv = xr[d];
        float4 w = *(const float4*)&W1[d * 64 + c4];
        acc.x = fmaf(xv, w.x, acc.x);
        acc.y = fmaf(xv, w.y, acc.y);
        acc.z = fmaf(xv, w.z, acc.z);
        acc.w = fmaf(xv, w.w, acc.w);
    }
    *(float4*)&g_G[(size_t)(i0 + p) * 64 + c4] = acc;
}

// ---------------------------------------------------------------------------
// Main edge kernel: one block per point, 128 threads.
// Phase A (fp32): h1 = relu(G[j] + rel @ W1[64:67]) -> bf16 hi/lo planes,
//                 layout [nbr][d], row stride 72 halves (ldmatrix-ready).
// Phase B (HMMA): D[128c][64nbr] = W2T_hi*Bhi + W2T_hi*Blo + W2T_lo*Bhi via
//                 mma.sync m16n8k16; per warp 32 channels x 64 nbrs, A frags
//                 pre-baked in gmem, B frags via plain ldmatrix. Max over
//                 cols in-register + quad shfl reduce, +b2, ReLU.
// ---------------------------------------------------------------------------
__global__ void __launch_bounds__(128) compute_kernel(
    const float* __restrict__ pos, const float* __restrict__ W1,
    const float* __restrict__ b2, int n)
{
    __shared__ __align__(16) unsigned short BHIs[KNBR * BSTRIDE];
    __shared__ __align__(16) unsigned short BLOs[KNBR * BSTRIDE];
    __shared__ int   nbr_s[KNBR];
    __shared__ float relx[KNBR], rely[KNBR], relz[KNBR];
    __shared__ float red[H2DIM];

    const int i    = blockIdx.x;
    const int tid  = threadIdx.x;
    const int wid  = tid >> 5;
    const int lane = tid & 31;
    if (i >= n) return;

    if (tid < KNBR) {
        const int j = g_nbr[i * KNBR + tid];
        nbr_s[tid] = j;
        relx[tid] = pos[3 * j + 0] - pos[3 * i + 0];
        rely[tid] = pos[3 * j + 1] - pos[3 * i + 1];
        relz[tid] = pos[3 * j + 2] - pos[3 * i + 2];
    }
    __syncthreads();

    // ---- Phase A: fp32 h1 -> bf16 hi/lo planes, [nbr][d] stride 72 halves ----
    {
        const int nk0 = tid & 7;
        const int c4  = (tid >> 3) * 4;

        float4 g4[8];
        #pragma unroll
        for (int it = 0; it < 8; it++)
            g4[it] = *(const float4*)&g_G[(size_t)nbr_s[nk0 + it * 8] * 64 + c4];

        const float4 wx = *(const float4*)&W1[64 * 64 + c4];
        const float4 wy = *(const float4*)&W1[65 * 64 + c4];
        const float4 wz = *(const float4*)&W1[66 * 64 + c4];

        #pragma unroll
        for (int it = 0; it < 8; it++) {
            const int nk = nk0 + it * 8;
            const float rx = relx[nk], ry = rely[nk], rz = relz[nk];
            float h0 = fmaxf(fmaf(rx, wx.x, fmaf(ry, wy.x, fmaf(rz, wz.x, g4[it].x))), 0.0f);
            float h1 = fmaxf(fmaf(rx, wx.y, fmaf(ry, wy.y, fmaf(rz, wz.y, g4[it].y))), 0.0f);
            float h2 = fmaxf(fmaf(rx, wx.z, fmaf(ry, wy.z, fmaf(rz, wz.z, g4[it].z))), 0.0f);
            float h3 = fmaxf(fmaf(rx, wx.w, fmaf(ry, wy.w, fmaf(rz, wz.w, g4[it].w))), 0.0f);

            const unsigned b0 = bf16rn(h0), b1v = bf16rn(h1);
            const unsigned b2v = bf16rn(h2), b3 = bf16rn(h3);
            const unsigned l0 = bf16rn(h0 - __uint_as_float(b0 << 16));
            const unsigned l1 = bf16rn(h1 - __uint_as_float(b1v << 16));
            const unsigned l2 = bf16rn(h2 - __uint_as_float(b2v << 16));
            const unsigned l3 = bf16rn(h3 - __uint_as_float(b3 << 16));

            const ull hiw = (ull)(b0 | (b1v << 16)) | ((ull)(b2v | (b3 << 16)) << 32);
            const ull low = (ull)(l0 | (l1 << 16)) | ((ull)(l2 | (l3 << 16)) << 32);
            *(ull*)&BHIs[nk * BSTRIDE + c4] = hiw;
            *(ull*)&BLOs[nk * BSTRIDE + c4] = low;
        }
    }
    __syncthreads();

    // ---- Phase B: mma.sync layer 2 + max-agg ----
    {
        const uint32_t bhi_base = smem_to_u32(BHIs);
        const uint32_t blo_base = smem_to_u32(BLOs);
        const int g  = lane >> 3;      // ldmatrix lane group 0..3
        const int gr = lane & 7;

        float mx[2][2] = {{-1e30f, -1e30f}, {-1e30f, -1e30f}};   // [mt][rowhalf]

        #pragma unroll
        for (int nh = 0; nh < 2; nh++) {
            float acc[2][4][4];
            #pragma unroll
            for (int mt = 0; mt < 2; mt++)
                #pragma unroll
                for (int nt = 0; nt < 4; nt++)
                    #pragma unroll
                    for (int e = 0; e < 4; e++) acc[mt][nt][e] = 0.0f;

            #pragma unroll
            for (int kt = 0; kt < 4; kt++) {
                // A fragments (pre-baked, coalesced LDG.128)
                uint4 ah[2], al[2];
                ah[0] = g_AF4[(((wid * 2 + 0) * 4 + kt) * 2 + 0) * 32 + lane];
                ah[1] = g_AF4[(((wid * 2 + 1) * 4 + kt) * 2 + 0) * 32 + lane];
                al[0] = g_AF4[(((wid * 2 + 0) * 4 + kt) * 2 + 1) * 32 + lane];
                al[1] = g_AF4[(((wid * 2 + 1) * 4 + kt) * 2 + 1) * 32 + lane];

                // B fragments via plain ldmatrix.x4:
                // groups: g0=(n+0..7,k lo) g1=(n+0..7,k hi) g2=(n+8..15,k lo) g3=(n+8..15,k hi)
                uint32_t bh[4][2], bl[4][2];
                #pragma unroll
                for (int ntp = 0; ntp < 2; ntp++) {
                    const int row = nh * 32 + ntp * 16 + (g >> 1) * 8 + gr;
                    const uint32_t off = (uint32_t)(row * (BSTRIDE * 2) + (kt * 16 + (g & 1) * 8) * 2);
                    uint32_t r0, r1, r2, r3;
                    LDSM_X4(r0, r1, r2, r3, bhi_base + off);
                    bh[2 * ntp][0] = r0; bh[2 * ntp][1] = r1;
                    bh[2 * ntp + 1][0] = r2; bh[2 * ntp + 1][1] = r3;
                    LDSM_X4(r0, r1, r2, r3, blo_base + off);
                    bl[2 * ntp][0] = r0; bl[2 * ntp][1] = r1;
                    bl[2 * ntp + 1][0] = r2; bl[2 * ntp + 1][1] = r3;
                }

                #pragma unroll
                for (int mt = 0; mt < 2; mt++)
                    #pragma unroll
                    for (int nt = 0; nt < 4; nt++) {
                        MMA_BF16(acc[mt][nt], ah[mt], bh[nt][0], bh[nt][1]);
                        MMA_BF16(acc[mt][nt], ah[mt], bl[nt][0], bl[nt][1]);
                        MMA_BF16(acc[mt][nt], al[mt], bh[nt][0], bh[nt][1]);
                    }
            }

            // fold this n-half into running maxes
            #pragma unroll
            for (int mt = 0; mt < 2; mt++)
                #pragma unroll
                for (int nt = 0; nt < 4; nt++) {
                    mx[mt][0] = fmaxf(mx[mt][0], fmaxf(acc[mt][nt][0], acc[mt][nt][1]));
                    mx[mt][1] = fmaxf(mx[mt][1], fmaxf(acc[mt][nt][2], acc[mt][nt][3]));
                }
        }

        // quad reduction: lanes sharing l/4 hold the same rows
        #pragma unroll
        for (int mt = 0; mt < 2; mt++)
            #pragma unroll
            for (int h = 0; h < 2; h++) {
                float v = mx[mt][h];
                v = fmaxf(v, __shfl_xor_sync(0xffffffffu, v, 1));
                v = fmaxf(v, __shfl_xor_sync(0xffffffffu, v, 2));
                mx[mt][h] = v;
            }
        if ((lane & 3) == 0) {
            const int q = lane >> 2;
            red[32 * wid + q]      = mx[0][0];
            red[32 * wid + 8 + q]  = mx[0][1];
            red[32 * wid + 16 + q] = mx[1][0];
            red[32 * wid + 24 + q] = mx[1][1];
        }
    }
    __syncthreads();

    // relu(max + b2) == max relu(z + b2)  (max monotone)
    g_AGG[(size_t)i * H2DIM + tid] = fmaxf(red[tid] + b2[tid], 0.0f);
}

// ---------------------------------------------------------------------------
// Global layer GEMM: out = relu(AGG @ Wg + bg), packed f32x2.
// ---------------------------------------------------------------------------
__global__ void __launch_bounds__(256) gemm_kernel(
    const float* __restrict__ bg, float* __restrict__ out, int n)
{
    __shared__ __align__(16) float As[H2DIM * 36];
    const int tid = threadIdx.x;
    const int i0  = blockIdx.x * 32;

    for (int idx = tid; idx < 32 * H2DIM; idx += 256) {
        const int r = idx >> 7, d = idx & 127;
        const int row = (i0 + r < n) ? (i0 + r) : (n - 1);
        As[d * 36 + r] = g_AGG[(size_t)row * H2DIM + d];
    }
    __syncthreads();

    const int c = tid;
    ull acc[16];
    #pragma unroll
    for (int p = 0; p < 16; p++) acc[p] = 0ull;

    const ull* wp = reinterpret_cast<const ull*>(g_Wgd) + c;
    #pragma unroll 2
    for (int d = 0; d < H2DIM; d++) {
        const ull wd = *wp; wp += ODIM;
        const float* ar = &As[d * 36];
        #pragma unroll
        for (int p = 0; p < 8; p++) {
            const ulonglong2 av = *reinterpret_cast<const ulonglong2*>(ar + 4 * p);
            fma2(acc[2 * p + 0], av.x, wd);
            fma2(acc[2 * p + 1], av.y, wd);
        }
    }

    const float bc = bg[c];
    #pragma unroll
    for (int k = 0; k < 16; k++) {
        const float lo = __uint_as_float((unsigned)(acc[k] & 0xffffffffu));
        const float hi = __uint_as_float((unsigned)(acc[k] >> 32));
        const int r0 = i0 + 2 * k, r1 = r0 + 1;
        if (r0 < n) out[(size_t)r0 * ODIM + c] = fmaxf(lo + bc, 0.0f);
        if (r1 < n) out[(size_t)r1 * ODIM + c] = fmaxf(hi + bc, 0.0f);
    }
}

// ---------------------------------------------------------------------------
extern "C" void kernel_launch(void* const* d_in, const int* in_sizes, int n_in,
                              void* d_out, int out_size)
{
    const float* x   = (const float*)d_in[0];
    const float* pos = (const float*)d_in[1];
    // d_in[2] = batch (all zeros, unused)
    const float* W1  = (const float*)d_in[3];
    const float* b1  = (const float*)d_in[4];
    const float* W2  = (const float*)d_in[5];
    const float* b2  = (const float*)d_in[6];
    const float* Wg  = (const float*)d_in[7];
    const float* bg  = (const float*)d_in[8];
    float* out = (float*)d_out;

    const int n = in_sizes[2];

    int prep_work = H2DIM * ODIM + 64 * 32;
    if (n > prep_work) prep_work = n;
    prep_kernel<<<(prep_work + 255) / 256, 256>>>(W2, Wg, pos, n);
    hist_kernel<<<(n + 255) / 256, 256>>>(n);
    scan_kernel<<<1, NCELLS>>>();
    scatter_kernel<<<(n + 255) / 256, 256>>>(n);
    knn_kernel<<<(n + 3) / 4, 128>>>(n);
    g_kernel<<<(n + 7) / 8, 128>>>(x, W1, b1, n);
    compute_kernel<<<n, 128>>>(pos, W1, b2, n);
    gemm_kernel<<<(n + 31) / 32, 256>>>(bg, out, n);
}

// round 13
// speedup vs baseline: 3.1698x; 1.0139x over previous
#include <cuda_runtime.h>
#include <cuda_bf16.h>
#include <cstdint>

#define NPTS   8192
#define KNBR   64
#define CIN    64
#define H1DIM  64
#define H2DIM  128
#define ODIM   256
#define R2     0.015625f   // 0.125^2 exactly
#define CAP    192         // candidate cap (mean ~60 in-radius)
#define GRID   8           // 8x8x8 cells, width 0.125 == R
#define NCELLS (GRID * GRID * GRID)

#define BSTRIDE 72         // halves per row of B planes (144B, 16B-aligned, conflict-free)

typedef unsigned long long ull;

// ---- scratch (device globals; no allocation allowed) ----------------------
__device__ int    g_nbr[NPTS * KNBR];
__device__ float  g_G  [NPTS * CIN];        // x @ W1[:64] + b1
__device__ float  g_AGG[NPTS * H2DIM];      // max-aggregated h2
__device__ float2 g_Wgd[H2DIM * ODIM];      // Wg duplicated (w,w)
__device__ float4 g_pos4[NPTS];             // (x, y, z, |p|^2)
__device__ uint4  g_AF4[64 * 32];           // pre-baked W2^T mma A-fragments
                                            // frag = ((w*2+mt)*4+kt)*2+plane, [frag][lane]
// spatial grid (cnt/fill are zero at entry of every call: zero-init at load,
// re-zeroed by scan_kernel each call after it consumes them -> replay-safe)
__device__ int    g_cell_cnt[NCELLS];
__device__ int    g_cell_start[NCELLS];
__device__ int    g_cell_end[NCELLS];
__device__ int    g_cell_fill[NCELLS];
__device__ float4 g_pos4s[NPTS];
__device__ int    g_ptid[NPTS];

__device__ __forceinline__ void fma2(ull& d, ull a, ull b) {
    asm("fma.rn.f32x2 %0, %1, %2, %0;" : "+l"(d) : "l"(a), "l"(b));
}
__device__ __forceinline__ int cell_of(float v) {
    int c = (int)(v * (float)GRID);
    return min(max(c, 0), GRID - 1);
}
// round-to-nearest-even fp32 -> bf16 (bits)  (prep-side; matches cvt.rn)
__device__ __forceinline__ unsigned bf16rn(float f) {
    unsigned u = __float_as_uint(f);
    return (u + 0x7FFFu + ((u >> 16) & 1u)) >> 16;
}
// hardware pack: bits[15:0] = bf16rn(a), bits[31:16] = bf16rn(b)
__device__ __forceinline__ uint32_t pack_bf16x2(float a, float b) {
    uint32_t r;
    asm("cvt.rn.bf16x2.f32 %0, %1, %2;" : "=r"(r) : "f"(b), "f"(a));
    return r;
}
__device__ __forceinline__ uint32_t smem_to_u32(const void* p) {
    uint32_t a;
    asm("{ .reg .u64 t; cvta.to.shared.u64 t, %1; cvt.u32.u64 %0, t; }" : "=r"(a) : "l"(p));
    return a;
}

// mma.sync m16n8k16 bf16, fp32 accum (baseline PTX; valid on compute_103)
#define MMA_BF16(acc, a, b0v, b1v) \
    asm volatile("mma.sync.aligned.m16n8k16.row.col.f32.bf16.bf16.f32 " \
        "{%0,%1,%2,%3}, {%4,%5,%6,%7}, {%8,%9}, {%0,%1,%2,%3};" \
        : "+f"((acc)[0]), "+f"((acc)[1]), "+f"((acc)[2]), "+f"((acc)[3]) \
        : "r"((a).x), "r"((a).y), "r"((a).z), "r"((a).w), "r"(b0v), "r"(b1v))

#define LDSM_X4(r0, r1, r2, r3, addr) \
    asm volatile("ldmatrix.sync.aligned.m8n8.x4.shared.b16 {%0,%1,%2,%3}, [%4];" \
        : "=r"(r0), "=r"(r1), "=r"(r2), "=r"(r3) : "r"(addr))

// ---------------------------------------------------------------------------
// Prep: Wg dup pairs; pos4 pack + cell histogram (hist fused); bake W2^T
// A-fragments for mma.
// ---------------------------------------------------------------------------
__global__ void prep_kernel(const float* __restrict__ W2, const float* __restrict__ Wg,
                            const float* __restrict__ pos, int n)
{
    int t = blockIdx.x * 256 + threadIdx.x;
    if (t < H2DIM * ODIM) {
        float w = Wg[t];
        g_Wgd[t] = make_float2(w, w);
    }
    if (t < n) {
        const float px = pos[3 * t + 0];
        const float py = pos[3 * t + 1];
        const float pz = pos[3 * t + 2];
        g_pos4[t] = make_float4(px, py, pz, px * px + py * py + pz * pz);
        const int c = (cell_of(pz) * GRID + cell_of(py)) * GRID + cell_of(px);
        atomicAdd(&g_cell_cnt[c], 1);      // cnt is zero at entry (see scan)
    }
    // A-fragment baking: a0=(r,k), a1=(r+8,k), a2=(r,k+8), a3=(r+8,k+8);
    // per-lane: row = base_m + lane/4, k = base_k + 2*(lane%4)+{0,1}
    int t4 = t - H2DIM * ODIM;
    if (t4 >= 0 && t4 < 64 * 32) {
        const int frag = t4 >> 5, lane = t4 & 31;
        const int plane = frag & 1;
        const int kt    = (frag >> 1) & 3;
        const int mt    = (frag >> 3) & 1;
        const int ww    = frag >> 4;
        const int r = 32 * ww + 16 * mt + (lane >> 2);
        const int k = 16 * kt + 2 * (lane & 3);
        uint32_t regs[4];
        #pragma unroll
        for (int j = 0; j < 4; j++) {
            const int rr = r + (j & 1) * 8;
            const int kk = k + (j >> 1) * 8;
            const float v0 = W2[(size_t)kk * H2DIM + rr];       // W2^T[rr][kk]
            const float v1 = W2[(size_t)(kk + 1) * H2DIM + rr];
            unsigned h0 = bf16rn(v0), h1 = bf16rn(v1);
            if (plane) {
                h0 = bf16rn(v0 - __uint_as_float(h0 << 16));
                h1 = bf16rn(v1 - __uint_as_float(h1 << 16));
            }
            regs[j] = h0 | (h1 << 16);
        }
        g_AF4[frag * 32 + lane] = make_uint4(regs[0], regs[1], regs[2], regs[3]);
    }
}

// ---------------------------------------------------------------------------
// Scan: counts -> start/end; then zero cnt/fill for the next replay.
// ---------------------------------------------------------------------------
__global__ void scan_kernel()
{
    __shared__ int buf[NCELLS];
    const int t = threadIdx.x;
    const int v = g_cell_cnt[t];
    buf[t] = v;
    __syncthreads();
    for (int o = 1; o < NCELLS; o <<= 1) {
        int u = (t >= o) ? buf[t - o] : 0;
        __syncthreads();
        buf[t] += u;
        __syncthreads();
    }
    g_cell_start[t] = buf[t] - v;   // exclusive prefix
    g_cell_end[t]   = buf[t];       // inclusive end
    g_cell_cnt[t]   = 0;            // reset for next graph replay
    g_cell_fill[t]  = 0;
}

__global__ void scatter_kernel(int n)
{
    int t = blockIdx.x * 256 + threadIdx.x;
    if (t >= n) return;
    const float4 p = g_pos4[t];
    const int c = (cell_of(p.z) * GRID + cell_of(p.y)) * GRID + cell_of(p.x);
    const int slot = g_cell_start[c] + atomicAdd(&g_cell_fill[c], 1);
    g_pos4s[slot] = p;
    g_ptid[slot]  = t;
}

// ---------------------------------------------------------------------------
// Grid KNN: one warp per target; 27-cell sweep (cell width == R covers all).
// ---------------------------------------------------------------------------
__global__ void __launch_bounds__(128) knn_kernel(int n)
{
    __shared__ float cd2 [4][CAP];
    __shared__ int   cidx[4][CAP];
    __shared__ int   cnt[4];

    const int w    = threadIdx.x >> 5;
    const int lane = threadIdx.x & 31;
    const int i    = blockIdx.x * 4 + w;
    if (i >= n) return;
    if (lane == 0) cnt[w] = 0;
    __syncwarp();

    const float4 q = g_pos4[i];
    const int cx = cell_of(q.x), cy = cell_of(q.y), cz = cell_of(q.z);

    const int zlo = max(cz - 1, 0), zhi = min(cz + 1, GRID - 1);
    const int ylo = max(cy - 1, 0), yhi = min(cy + 1, GRID - 1);
    const int xlo = max(cx - 1, 0), xhi = min(cx + 1, GRID - 1);

    for (int z = zlo; z <= zhi; z++)
        for (int y = ylo; y <= yhi; y++) {
            const int c0 = (z * GRID + y) * GRID + xlo;
            const int c1 = (z * GRID + y) * GRID + xhi;
            const int s0 = g_cell_start[c0];
            const int s1 = g_cell_end[c1];
            for (int s = s0 + lane; s < s1; s += 32) {
                const float4 p = g_pos4s[s];
                const float dot = p.x * q.x + p.y * q.y + p.z * q.z;
                const float d2  = (q.w + p.w) - 2.0f * dot;
                if (d2 <= R2) {
                    int slot = atomicAdd(&cnt[w], 1);
                    if (slot < CAP) { cd2[w][slot] = d2; cidx[w][slot] = g_ptid[s]; }
                }
            }
        }
    __syncwarp();

    int M = cnt[w]; if (M > CAP) M = CAP;

    if (M <= KNBR) {
        for (int l = lane; l < KNBR; l += 32)
            g_nbr[i * KNBR + l] = (l < M) ? cidx[w][l] : i;
    } else {
        for (int m = lane; m < M; m += 32) {
            const float dm = cd2[w][m];
            const int   im = cidx[w][m];
            int rank = 0;
            for (int qq = 0; qq < M; qq++) {
                const float dq = cd2[w][qq];
                rank += (dq < dm) || (dq == dm && cidx[w][qq] < im);
            }
            if (rank < KNBR) g_nbr[i * KNBR + rank] = cidx[w][m];
        }
    }
}

// ---------------------------------------------------------------------------
// G precompute: G = x @ W1[0:64,:] + b1
// ---------------------------------------------------------------------------
__global__ void __launch_bounds__(128) g_kernel(
    const float* __restrict__ x, const float* __restrict__ W1,
    const float* __restrict__ b1, int n)
{
    __shared__ __align__(16) float xs[8 * 64];
    const int tid = threadIdx.x;
    const int i0  = blockIdx.x * 8;

    for (int idx = tid; idx < 512; idx += 128) {
        int p = idx >> 6, d = idx & 63;
        xs[idx] = (i0 + p < n) ? x[(size_t)(i0 + p) * 64 + d] : 0.0f;
    }
    __syncthreads();

    const int p  = tid >> 4;
    const int c4 = (tid & 15) * 4;
    if (i0 + p >= n) return;

    float4 acc = *(const float4*)&b1[c4];
    const float* xr = &xs[p * 64];
    #pragma unroll 8
    for (int d = 0; d < 64; d++) {
        const float xv = xr[d];
        float4 w = *(const float4*)&W1[d * 64 + c4];
        acc.x = fmaf(xv, w.x, acc.x);
        acc.y = fmaf(xv, w.y, acc.y);
        acc.z = fmaf(xv, w.z, acc.z);
        acc.w = fmaf(xv, w.w, acc.w);
    }
    *(float4*)&g_G[(size_t)(i0 + p) * 64 + c4] = acc;
}

// ---------------------------------------------------------------------------
// Main edge kernel: one block per point, 128 threads.
// Phase A (fp32): h1 = relu(G[j] + rel @ W1[64:67]) -> bf16 hi/lo planes
//                 via hardware cvt.rn.bf16x2, layout [nbr][d] stride 72.
// Phase B (HMMA): D[128c][64nbr] = W2T_hi*Bhi + W2T_hi*Blo + W2T_lo*Bhi via
//                 mma.sync m16n8k16; A frags pre-baked in gmem, B frags via
//                 plain ldmatrix. Max over cols + quad shfl reduce, +b2, ReLU.
// ---------------------------------------------------------------------------
__global__ void __launch_bounds__(128) compute_kernel(
    const float* __restrict__ pos, const float* __restrict__ W1,
    const float* __restrict__ b2, int n)
{
    __shared__ __align__(16) unsigned short BHIs[KNBR * BSTRIDE];
    __shared__ __align__(16) unsigned short BLOs[KNBR * BSTRIDE];
    __shared__ int   nbr_s[KNBR];
    __shared__ float relx[KNBR], rely[KNBR], relz[KNBR];
    __shared__ float red[H2DIM];

    const int i    = blockIdx.x;
    const int tid  = threadIdx.x;
    const int wid  = tid >> 5;
    const int lane = tid & 31;
    if (i >= n) return;

    if (tid < KNBR) {
        const int j = g_nbr[i * KNBR + tid];
        nbr_s[tid] = j;
        relx[tid] = pos[3 * j + 0] - pos[3 * i + 0];
        rely[tid] = pos[3 * j + 1] - pos[3 * i + 1];
        relz[tid] = pos[3 * j + 2] - pos[3 * i + 2];
    }
    __syncthreads();

    // ---- Phase A: fp32 h1 -> bf16 hi/lo planes, [nbr][d] stride 72 halves ----
    {
        const int nk0 = tid & 7;
        const int c4  = (tid >> 3) * 4;

        float4 g4[8];
        #pragma unroll
        for (int it = 0; it < 8; it++)
            g4[it] = *(const float4*)&g_G[(size_t)nbr_s[nk0 + it * 8] * 64 + c4];

        const float4 wx = *(const float4*)&W1[64 * 64 + c4];
        const float4 wy = *(const float4*)&W1[65 * 64 + c4];
        const float4 wz = *(const float4*)&W1[66 * 64 + c4];

        #pragma unroll
        for (int it = 0; it < 8; it++) {
            const int nk = nk0 + it * 8;
            const float rx = relx[nk], ry = rely[nk], rz = relz[nk];
            float h0 = fmaxf(fmaf(rx, wx.x, fmaf(ry, wy.x, fmaf(rz, wz.x, g4[it].x))), 0.0f);
            float h1 = fmaxf(fmaf(rx, wx.y, fmaf(ry, wy.y, fmaf(rz, wz.y, g4[it].y))), 0.0f);
            float h2 = fmaxf(fmaf(rx, wx.z, fmaf(ry, wy.z, fmaf(rz, wz.z, g4[it].z))), 0.0f);
            float h3 = fmaxf(fmaf(rx, wx.w, fmaf(ry, wy.w, fmaf(rz, wz.w, g4[it].w))), 0.0f);

            // hi planes via hardware cvt (RN-even, same as before bit-for-bit)
            const uint32_t p01 = pack_bf16x2(h0, h1);
            const uint32_t p23 = pack_bf16x2(h2, h3);
            // hi-as-float for residuals: 1 LOP each
            const float f0 = __uint_as_float(p01 << 16);
            const float f1 = __uint_as_float(p01 & 0xFFFF0000u);
            const float f2 = __uint_as_float(p23 << 16);
            const float f3 = __uint_as_float(p23 & 0xFFFF0000u);
            const uint32_t q01 = pack_bf16x2(h0 - f0, h1 - f1);
            const uint32_t q23 = pack_bf16x2(h2 - f2, h3 - f3);

            const ull hiw = (ull)p01 | ((ull)p23 << 32);
            const ull low = (ull)q01 | ((ull)q23 << 32);
            *(ull*)&BHIs[nk * BSTRIDE + c4] = hiw;
            *(ull*)&BLOs[nk * BSTRIDE + c4] = low;
        }
    }
    __syncthreads();

    // ---- Phase B: mma.sync layer 2 + max-agg ----
    {
        const uint32_t bhi_base = smem_to_u32(BHIs);
        const uint32_t blo_base = smem_to_u32(BLOs);
        const int g  = lane >> 3;      // ldmatrix lane group 0..3
        const int gr = lane & 7;

        float mx[2][2] = {{-1e30f, -1e30f}, {-1e30f, -1e30f}};   // [mt][rowhalf]

        #pragma unroll
        for (int nh = 0; nh < 2; nh++) {
            float acc[2][4][4];
            #pragma unroll
            for (int mt = 0; mt < 2; mt++)
                #pragma unroll
                for (int nt = 0; nt < 4; nt++)
                    #pragma unroll
                    for (int e = 0; e < 4; e++) acc[mt][nt][e] = 0.0f;

            #pragma unroll
            for (int kt = 0; kt < 4; kt++) {
                // A fragments (pre-baked, coalesced LDG.128, L1-hot)
                uint4 ah[2], al[2];
                ah[0] = g_AF4[(((wid * 2 + 0) * 4 + kt) * 2 + 0) * 32 + lane];
                ah[1] = g_AF4[(((wid * 2 + 1) * 4 + kt) * 2 + 0) * 32 + lane];
                al[0] = g_AF4[(((wid * 2 + 0) * 4 + kt) * 2 + 1) * 32 + lane];
                al[1] = g_AF4[(((wid * 2 + 1) * 4 + kt) * 2 + 1) * 32 + lane];

                // B fragments via plain ldmatrix.x4
                uint32_t bh[4][2], bl[4][2];
                #pragma unroll
                for (int ntp = 0; ntp < 2; ntp++) {
                    const int row = nh * 32 + ntp * 16 + (g >> 1) * 8 + gr;
                    const uint32_t off = (uint32_t)(row * (BSTRIDE * 2) + (kt * 16 + (g & 1) * 8) * 2);
                    uint32_t r0, r1, r2, r3;
                    LDSM_X4(r0, r1, r2, r3, bhi_base + off);
                    bh[2 * ntp][0] = r0; bh[2 * ntp][1] = r1;
                    bh[2 * ntp + 1][0] = r2; bh[2 * ntp + 1][1] = r3;
                    LDSM_X4(r0, r1, r2, r3, blo_base + off);
                    bl[2 * ntp][0] = r0; bl[2 * ntp][1] = r1;
                    bl[2 * ntp + 1][0] = r2; bl[2 * ntp + 1][1] = r3;
                }

                #pragma unroll
                for (int mt = 0; mt < 2; mt++)
                    #pragma unroll
                    for (int nt = 0; nt < 4; nt++) {
                        MMA_BF16(acc[mt][nt], ah[mt], bh[nt][0], bh[nt][1]);
                        MMA_BF16(acc[mt][nt], ah[mt], bl[nt][0], bl[nt][1]);
                        MMA_BF16(acc[mt][nt], al[mt], bh[nt][0], bh[nt][1]);
                    }
            }

            // fold this n-half into running maxes
            #pragma unroll
            for (int mt = 0; mt < 2; mt++)
                #pragma unroll
                for (int nt = 0; nt < 4; nt++) {
                    mx[mt][0] = fmaxf(mx[mt][0], fmaxf(acc[mt][nt][0], acc[mt][nt][1]));
                    mx[mt][1] = fmaxf(mx[mt][1], fmaxf(acc[mt][nt][2], acc[mt][nt][3]));
                }
        }

        // quad reduction: lanes sharing l/4 hold the same rows
        #pragma unroll
        for (int mt = 0; mt < 2; mt++)
            #pragma unroll
            for (int h = 0; h < 2; h++) {
                float v = mx[mt][h];
                v = fmaxf(v, __shfl_xor_sync(0xffffffffu, v, 1));
                v = fmaxf(v, __shfl_xor_sync(0xffffffffu, v, 2));
                mx[mt][h] = v;
            }
        if ((lane & 3) == 0) {
            const int q = lane >> 2;
            red[32 * wid + q]      = mx[0][0];
            red[32 * wid + 8 + q]  = mx[0][1];
            red[32 * wid + 16 + q] = mx[1][0];
            red[32 * wid + 24 + q] = mx[1][1];
        }
    }
    __syncthreads();

    // relu(max + b2) == max relu(z + b2)  (max monotone)
    g_AGG[(size_t)i * H2DIM + tid] = fmaxf(red[tid] + b2[tid], 0.0f);
}

// ---------------------------------------------------------------------------
// Global layer GEMM: out = relu(AGG @ Wg + bg), packed f32x2.
// ---------------------------------------------------------------------------
__global__ void __launch_bounds__(256) gemm_kernel(
    const float* __restrict__ bg, float* __restrict__ out, int n)
{
    __shared__ __align__(16) float As[H2DIM * 36];
    const int tid = threadIdx.x;
    const int i0  = blockIdx.x * 32;

    for (int idx = tid; idx < 32 * H2DIM; idx += 256) {
        const int r = idx >> 7, d = idx & 127;
        const int row = (i0 + r < n) ? (i0 + r) : (n - 1);
        As[d * 36 + r] = g_AGG[(size_t)row * H2DIM + d];
    }
    __syncthreads();

    const int c = tid;
    ull acc[16];
    #pragma unroll
    for (int p = 0; p < 16; p++) acc[p] = 0ull;

    const ull* wp = reinterpret_cast<const ull*>(g_Wgd) + c;
    #pragma unroll 2
    for (int d = 0; d < H2DIM; d++) {
        const ull wd = *wp; wp += ODIM;
        const float* ar = &As[d * 36];
        #pragma unroll
        for (int p = 0; p < 8; p++) {
            const ulonglong2 av = *reinterpret_cast<const ulonglong2*>(ar + 4 * p);
            fma2(acc[2 * p + 0], av.x, wd);
            fma2(acc[2 * p + 1], av.y, wd);
        }
    }

    const float bc = bg[c];
    #pragma unroll
    for (int k = 0; k < 16; k++) {
        const float lo = __uint_as_float((unsigned)(acc[k] & 0xffffffffu));
        const float hi = __uint_as_float((unsigned)(acc[k] >> 32));
        const int r0 = i0 + 2 * k, r1 = r0 + 1;
        if (r0 < n) out[(size_t)r0 * ODIM + c] = fmaxf(lo + bc, 0.0f);
        if (r1 < n) out[(size_t)r1 * ODIM + c] = fmaxf(hi + bc, 0.0f);
    }
}

// ---------------------------------------------------------------------------
extern "C" void kernel_launch(void* const* d_in, const int* in_sizes, int n_in,
                              void* d_out, int out_size)
{
    const float* x   = (const float*)d_in[0];
    const float* pos = (const float*)d_in[1];
    // d_in[2] = batch (all zeros, unused)
    const float* W1  = (const float*)d_in[3];
    const float* b1  = (const float*)d_in[4];
    const float* W2  = (const float*)d_in[5];
    const float* b2  = (const float*)d_in[6];
    const float* Wg  = (const float*)d_in[7];
    const float* bg  = (const float*)d_in[8];
    float* out = (float*)d_out;

    const int n = in_sizes[2];

    int prep_work = H2DIM * ODIM + 64 * 32;
    if (n > prep_work) prep_work = n;
    prep_kernel<<<(prep_work + 255) / 256, 256>>>(W2, Wg, pos, n);
    scan_kernel<<<1, NCELLS>>>();
    scatter_kernel<<<(n + 255) / 256, 256>>>(n);
    knn_kernel<<<(n + 3) / 4, 128>>>(n);
    g_kernel<<<(n + 7) / 8, 128>>>(x, W1, b1, n);
    compute_kernel<<<n, 128>>>(pos, W1, b2, n);
    gemm_kernel<<<(n + 31) / 32, 256>>>(bg, out, n);
}